// round 7
// baseline (speedup 1.0000x reference)
#include <cuda_runtime.h>
#include <math.h>

// ---------------------------------------------------------------------------
// out = gelu_tanh(x) * gate(row)
// gate = exp(-tau*cos) * (1 + w*relu(tanh(sigma*mean|z|) - surp_ema))
// x [4,4096,2048] fp32 -> 16384 rows, D=2048.
//
// Warp-autonomous design: ONE WARP OWNS ONE ROW. No smem, no block barriers.
// Phase 1: stream row, accumulate 3 sums, warp shuffle-reduce, gate.
// Phase 2: re-read row (L2-resident), recompute gelu, scale, streaming store.
// Channel stats precomputed by prep kernel into __device__ globals (L1-hot).
// ---------------------------------------------------------------------------

#define DIM 2048
#define ROWS_PER_WARP 2

__device__ float g_is[DIM];    // 1/(std+1e-5)
__device__ float g_nm[DIM];    // -mu * is
__device__ float g_en[DIM];    // ema_out normalized
__device__ float g_scal[4];    // ntau_l2e, sigma, w, surp

__device__ __forceinline__ float ex2f(float v) {
    float y; asm("ex2.approx.f32 %0, %1;" : "=f"(y) : "f"(v)); return y;
}
__device__ __forceinline__ float rcpf(float v) {
    float y; asm("rcp.approx.f32 %0, %1;" : "=f"(y) : "f"(v)); return y;
}
__device__ __forceinline__ float tanhf_hw(float v) {
    float y; asm("tanh.approx.f32 %0, %1;" : "=f"(y) : "f"(v)); return y;
}
__device__ __forceinline__ float softplus_f(float v) {
    return (v > 20.0f) ? v : log1pf(expf(v));
}
__device__ __forceinline__ float warp_sum(float v) {
    #pragma unroll
    for (int o = 16; o > 0; o >>= 1)
        v += __shfl_xor_sync(0xffffffffu, v, o);
    return v;
}

// gelu = 0.5x + 0.5x * tanh(x*(C1 + C2*x^2))
__device__ __forceinline__ float gelu_hw(float x) {
    const float C1 = 0.7978845608f;   // sqrt(2/pi)
    const float C2 = 0.0356774081f;   // C1 * 0.044715
    float u = x * fmaf(x * x, C2, C1);
    float t = tanhf_hw(u);
    float h = 0.5f * x;
    return fmaf(h, t, h);
}

__global__ void prep_kernel(const float* __restrict__ ema_mean,
                            const float* __restrict__ ema_sq,
                            const float* __restrict__ ema_out,
                            const float* __restrict__ surp_ema,
                            const float* __restrict__ log_tau,
                            const float* __restrict__ log_sigma,
                            const float* __restrict__ log_w) {
    __shared__ float red[8];
    int tid = threadIdx.x;
    int wid = tid >> 5;
    int lid = tid & 31;

    float ess = 0.0f;
    #pragma unroll
    for (int c = 0; c < 8; c++) {
        int d = tid + c * 256;
        float mu  = ema_mean[d];
        float var = fmaxf(ema_sq[d] - mu * mu, 1e-4f);
        float s   = 1.0f / (sqrtf(var) + 1e-5f);
        g_is[d] = s;
        g_nm[d] = -mu * s;
        float e = ema_out[d];
        ess = fmaf(e, e, ess);
    }
    ess = warp_sum(ess);
    if (lid == 0) red[wid] = ess;
    __syncthreads();
    float tot = red[0] + red[1] + red[2] + red[3]
              + red[4] + red[5] + red[6] + red[7];
    float inv_norm = 1.0f / fmaxf(sqrtf(tot), 1e-12f);
    #pragma unroll
    for (int c = 0; c < 8; c++) {
        int d = tid + c * 256;
        g_en[d] = ema_out[d] * inv_norm;
    }
    if (tid == 0) {
        g_scal[0] = -expf(log_tau[0]) * 1.44269504f;  // -tau*log2(e)
        g_scal[1] = softplus_f(log_sigma[0]);
        g_scal[2] = softplus_f(log_w[0]);
        g_scal[3] = surp_ema[0];
    }
}

__global__ __launch_bounds__(256, 6)
void fused_gelu_gate(const float* __restrict__ x,
                     float* __restrict__ out) {
    const int lid = threadIdx.x & 31;
    const int gwarp = (blockIdx.x * 256 + threadIdx.x) >> 5;

    const float ntl = __ldg(&g_scal[0]);
    const float sg  = __ldg(&g_scal[1]);
    const float w   = __ldg(&g_scal[2]);
    const float sp  = __ldg(&g_scal[3]);

    const float4* IS4 = (const float4*)g_is;
    const float4* NM4 = (const float4*)g_nm;
    const float4* EN4 = (const float4*)g_en;

    #pragma unroll 1
    for (int rr = 0; rr < ROWS_PER_WARP; rr++) {
        const long long row = (long long)gwarp * ROWS_PER_WARP + rr;
        const float4* xr = (const float4*)x + row * 512;
        float4*       orow = (float4*)out + row * 512;

        // ---- phase 1: stream row, accumulate sums ----
        float az = 0.f, sq = 0.f, dt = 0.f;
        #pragma unroll
        for (int k = 0; k < 16; k++) {
            const int idx = lid + k * 32;
            float4 xv = xr[idx];                 // default: caches L1+L2
            float4 is = __ldg(IS4 + idx);
            float4 nm = __ldg(NM4 + idx);
            float4 en = __ldg(EN4 + idx);
            const float* px = &xv.x;
            const float* pi = &is.x;
            const float* pn = &nm.x;
            const float* pe = &en.x;
            #pragma unroll
            for (int j = 0; j < 4; j++) {
                float xj = px[j];
                az += fabsf(fmaf(xj, pi[j], pn[j]));
                float o = gelu_hw(xj);
                sq = fmaf(o, o, sq);
                dt = fmaf(o, pe[j], dt);
            }
        }

        // ---- warp reduce (all lanes end with the full sums) ----
        az = warp_sum(az);
        sq = warp_sum(sq);
        dt = warp_sum(dt);

        // ---- gate (every lane redundantly) ----
        float surp_mod = fmaxf(tanhf_hw(sg * (az * (1.0f / 2048.0f))) - sp, 0.0f);
        float cs = dt * rsqrtf(fmaxf(sq, 1e-24f));
        cs = fminf(fmaxf(cs, -1.0f), 1.0f);
        float gate = ex2f(ntl * cs) * fmaf(w, surp_mod, 1.0f);

        // ---- phase 2: re-read row (L2 hit), gelu, scale, store ----
        #pragma unroll
        for (int k = 0; k < 16; k++) {
            const int idx = lid + k * 32;
            float4 xv = __ldcs(xr + idx);
            float4 o;
            o.x = gelu_hw(xv.x) * gate;
            o.y = gelu_hw(xv.y) * gate;
            o.z = gelu_hw(xv.z) * gate;
            o.w = gelu_hw(xv.w) * gate;
            __stcs(orow + idx, o);
        }
    }
}

extern "C" void kernel_launch(void* const* d_in, const int* in_sizes, int n_in,
                              void* d_out, int out_size) {
    const float* x        = (const float*)d_in[0];
    const float* ema_mean = (const float*)d_in[1];
    const float* ema_sq   = (const float*)d_in[2];
    const float* ema_out  = (const float*)d_in[3];
    const float* surp_ema = (const float*)d_in[4];
    const float* log_tau  = (const float*)d_in[5];
    const float* log_sig  = (const float*)d_in[6];
    const float* log_w    = (const float*)d_in[7];
    float* out = (float*)d_out;

    int D = in_sizes[1];                       // 2048
    long long total = (long long)in_sizes[0];  // 33554432
    int rows = (int)(total / D);               // 16384
    // 8 warps per CTA, ROWS_PER_WARP rows per warp
    int grid = rows / (8 * ROWS_PER_WARP);     // 1024

    prep_kernel<<<1, 256>>>(ema_mean, ema_sq, ema_out, surp_ema,
                            log_tau, log_sig, log_w);
    fused_gelu_gate<<<grid, 256>>>(x, out);
}

// round 8
// speedup vs baseline: 1.4903x; 1.4903x over previous
#include <cuda_runtime.h>
#include <cuda_fp16.h>
#include <math.h>

// ---------------------------------------------------------------------------
// out = gelu_tanh(x) * gate(row)
// gate = exp(-tau*cos) * (1 + w*relu(tanh(sigma*mean|z|) - surp_ema))
// x [4,4096,2048] fp32 -> 16384 rows, D=2048.
// CTA: 256 threads, 8 cols/thread (2x float4), 8 rows/CTA, depth-1 prefetch.
// z-path stats (is, nm) in HALF2 smem (halved LDS bytes, half2 vector math).
// en in fp32 smem. ONE barrier per row; every warp computes gate redundantly.
// ---------------------------------------------------------------------------

#define R_PER_CTA 8

__device__ __forceinline__ float ex2f(float v) {
    float y; asm("ex2.approx.f32 %0, %1;" : "=f"(y) : "f"(v)); return y;
}
__device__ __forceinline__ float rcpf(float v) {
    float y; asm("rcp.approx.f32 %0, %1;" : "=f"(y) : "f"(v)); return y;
}
__device__ __forceinline__ float tanhf_hw(float v) {
    float y; asm("tanh.approx.f32 %0, %1;" : "=f"(y) : "f"(v)); return y;
}
__device__ __forceinline__ float softplus_f(float v) {
    return (v > 20.0f) ? v : log1pf(expf(v));
}
__device__ __forceinline__ float warp_sum(float v) {
    #pragma unroll
    for (int o = 16; o > 0; o >>= 1)
        v += __shfl_xor_sync(0xffffffffu, v, o);
    return v;
}

// gelu = 0.5x + 0.5x * tanh(x*(C1 + C2*x^2))
__device__ __forceinline__ float gelu_hw(float x) {
    const float C1 = 0.7978845608f;   // sqrt(2/pi)
    const float C2 = 0.0356774081f;   // C1 * 0.044715
    float u = x * fmaf(x * x, C2, C1);
    float t = tanhf_hw(u);
    float h = 0.5f * x;
    return fmaf(h, t, h);
}

__global__ __launch_bounds__(256, 5)
void fused_gelu_gate(const float* __restrict__ x,
                     const float* __restrict__ ema_mean,
                     const float* __restrict__ ema_sq,
                     const float* __restrict__ ema_out,
                     const float* __restrict__ surp_ema,
                     const float* __restrict__ log_tau,
                     const float* __restrict__ log_sigma,
                     const float* __restrict__ log_w,
                     float* __restrict__ out) {
    const int D = 2048;
    const int tid = threadIdx.x;
    const int wid = tid >> 5;
    const int lid = tid & 31;
    const int i0 = tid;          // float4 index 0..255
    const int i1 = tid + 256;    // float4 index 256..511

    __shared__ __half2 s_is[1024];   // channel pairs: 1/(std+eps)
    __shared__ __half2 s_nm[1024];   // channel pairs: -mu*is
    __shared__ float   s_en[2048];   // normalized ema_out (fp32)
    __shared__ float4  red[2][8];
    __shared__ float   s_scal[4];    // ntau_l2e, sigma, w, surp

    const uint2*  IS2 = (const uint2*)s_is;   // 8B = 4 channels
    const uint2*  NM2 = (const uint2*)s_nm;
    const float4* EN4 = (const float4*)s_en;

    // ---- prologue: channel stats + scalars into smem ----
    {
        if (tid == 0) {
            s_scal[0] = -expf(log_tau[0]) * 1.44269504f;
            s_scal[1] = softplus_f(log_sigma[0]);
            s_scal[2] = softplus_f(log_w[0]);
            s_scal[3] = surp_ema[0];
        }
        const float4* M4 = (const float4*)ema_mean;
        const float4* Q4 = (const float4*)ema_sq;
        const float4* E4 = (const float4*)ema_out;
        float ess = 0.0f;
        #pragma unroll
        for (int c = 0; c < 2; c++) {
            int idx = (c == 0) ? i0 : i1;
            float4 m = M4[idx];
            float4 q = Q4[idx];
            float4 e = E4[idx];
            float iv[4], nv[4];
            float mm[4] = {m.x, m.y, m.z, m.w};
            float qq[4] = {q.x, q.y, q.z, q.w};
            #pragma unroll
            for (int j = 0; j < 4; j++) {
                float var = fmaxf(qq[j] - mm[j] * mm[j], 1e-4f);
                float s = rcpf(sqrtf(var) + 1e-5f);
                iv[j] = s;
                nv[j] = -mm[j] * s;
            }
            s_is[2 * idx]     = __floats2half2_rn(iv[0], iv[1]);
            s_is[2 * idx + 1] = __floats2half2_rn(iv[2], iv[3]);
            s_nm[2 * idx]     = __floats2half2_rn(nv[0], nv[1]);
            s_nm[2 * idx + 1] = __floats2half2_rn(nv[2], nv[3]);
            ((float4*)s_en)[idx] = e;
            ess = fmaf(e.x, e.x, ess);
            ess = fmaf(e.y, e.y, ess);
            ess = fmaf(e.z, e.z, ess);
            ess = fmaf(e.w, e.w, ess);
        }
        ess = warp_sum(ess);
        if (lid == 0) red[0][wid] = make_float4(ess, 0.f, 0.f, 0.f);
        __syncthreads();
        // all-warp reduce of the 8 partials
        float v = red[0][lid & 7].x;
        #pragma unroll
        for (int o = 1; o < 8; o <<= 1) v += __shfl_xor_sync(0xffffffffu, v, o);
        float inv_norm = rcpf(fmaxf(sqrtf(v), 1e-12f));
        #pragma unroll
        for (int c = 0; c < 2; c++) {
            int idx = (c == 0) ? i0 : i1;
            float4 e = ((float4*)s_en)[idx];
            e.x *= inv_norm; e.y *= inv_norm; e.z *= inv_norm; e.w *= inv_norm;
            ((float4*)s_en)[idx] = e;
        }
        __syncthreads();
    }

    // ---- row loop: depth-1 prefetch, one barrier per row ----
    long long row0 = (long long)blockIdx.x * R_PER_CTA;
    const float4* xbase4 = (const float4*)(x + row0 * D);
    float4*       obase4 = (float4*)(out + row0 * D);

    float4 ca = __ldcs(xbase4 + i0);
    float4 cb = __ldcs(xbase4 + i1);

    #pragma unroll 1
    for (int r = 0; r < R_PER_CTA; r++) {
        float4 na, nb;
        if (r < R_PER_CTA - 1) {
            const float4* xrn = xbase4 + (long long)(r + 1) * 512;
            na = __ldcs(xrn + i0);
            nb = __ldcs(xrn + i1);
        }

        __half2 az_h = __float2half2_rn(0.0f);
        float sq = 0.f, dt = 0.f;
        #pragma unroll
        for (int c = 0; c < 2; c++) {
            int idx = (c == 0) ? i0 : i1;
            float4& xv = (c == 0) ? ca : cb;

            uint2 isu = IS2[idx];
            uint2 nmu = NM2[idx];
            __half2 is0 = *reinterpret_cast<__half2*>(&isu.x);
            __half2 is1 = *reinterpret_cast<__half2*>(&isu.y);
            __half2 nm0 = *reinterpret_cast<__half2*>(&nmu.x);
            __half2 nm1 = *reinterpret_cast<__half2*>(&nmu.y);

            __half2 xh0 = __floats2half2_rn(xv.x, xv.y);
            __half2 xh1 = __floats2half2_rn(xv.z, xv.w);
            az_h = __hadd2(az_h, __habs2(__hfma2(xh0, is0, nm0)));
            az_h = __hadd2(az_h, __habs2(__hfma2(xh1, is1, nm1)));

            float4 en = EN4[idx];
            float* pv = &xv.x;
            const float* pe = &en.x;
            #pragma unroll
            for (int j = 0; j < 4; j++) {
                float o = gelu_hw(pv[j]);
                pv[j] = o;                   // in-place x -> gelu(x)
                sq = fmaf(o, o, sq);
                dt = fmaf(o, pe[j], dt);
            }
        }
        float2 azf = __half22float2(az_h);
        float az = azf.x + azf.y;

        az = warp_sum(az);
        sq = warp_sum(sq);
        dt = warp_sum(dt);
        if (lid == 0) red[r & 1][wid] = make_float4(az, sq, dt, 0.f);
        __syncthreads();

        // every warp reduces 8 partials + computes gate (no 2nd barrier)
        float4 v = red[r & 1][lid & 7];
        #pragma unroll
        for (int o = 1; o < 8; o <<= 1) {
            v.x += __shfl_xor_sync(0xffffffffu, v.x, o);
            v.y += __shfl_xor_sync(0xffffffffu, v.y, o);
            v.z += __shfl_xor_sync(0xffffffffu, v.z, o);
        }
        float ntl = s_scal[0], sg = s_scal[1], w = s_scal[2], sp = s_scal[3];
        float surp_mod = fmaxf(tanhf_hw(sg * (v.x * (1.0f / 2048.0f))) - sp, 0.0f);
        float cs = v.z * rsqrtf(fmaxf(v.y, 1e-24f));
        cs = fminf(fmaxf(cs, -1.0f), 1.0f);
        float gate = ex2f(ntl * cs) * fmaf(w, surp_mod, 1.0f);

        float4* orow = obase4 + (long long)r * 512;
        float4 o0 = {ca.x * gate, ca.y * gate, ca.z * gate, ca.w * gate};
        float4 o1 = {cb.x * gate, cb.y * gate, cb.z * gate, cb.w * gate};
        __stcs(orow + i0, o0);
        __stcs(orow + i1, o1);

        ca = na; cb = nb;
    }
}

extern "C" void kernel_launch(void* const* d_in, const int* in_sizes, int n_in,
                              void* d_out, int out_size) {
    const float* x        = (const float*)d_in[0];
    const float* ema_mean = (const float*)d_in[1];
    const float* ema_sq   = (const float*)d_in[2];
    const float* ema_out  = (const float*)d_in[3];
    const float* surp_ema = (const float*)d_in[4];
    const float* log_tau  = (const float*)d_in[5];
    const float* log_sig  = (const float*)d_in[6];
    const float* log_w    = (const float*)d_in[7];
    float* out = (float*)d_out;

    int D = in_sizes[1];                       // 2048
    long long total = (long long)in_sizes[0];  // 33554432
    int rows = (int)(total / D);               // 16384
    int grid = rows / R_PER_CTA;               // 2048

    fused_gelu_gate<<<grid, 256>>>(x, ema_mean, ema_sq, ema_out, surp_ema,
                                   log_tau, log_sig, log_w, out);
}